// round 2
// baseline (speedup 1.0000x reference)
#include <cuda_runtime.h>
#include <math.h>

// Problem constants
#define S_LEN 2048
#define D_DIM 64
#define F_DIM 16
#define NTOK  16384      // B*S = 8*2048
#define DIN   2112       // D + 2*D*F
#define NOUT  128        // O gate + O proj
#define NITER 66         // DIN/32

// ---------------- device scratch (static, allocation-free) ----------------
__device__ float g_f[D_DIM * F_DIM];          // freq_matrix * freq_scale
__device__ float g_walpha[4 * D_DIM];         // [h][d] folded alpha weights (incl 1/sqrt(8))
__device__ float g_calpha[4];                 // alpha bias
__device__ float g_ball[NOUT];                // bg | bp
__device__ float g_Wpack[DIN * NOUT];         // [k][o]: o<64 -> Wg[o][k], else Wp[o-64][k]
__device__ float g_trig[S_LEN * D_DIM * 32];  // [s][d][ sin(16) | cos(16) ]

// ---------------- f32x2 helpers (packed dual fp32 FMA, sm_100+) ----------------
__device__ __forceinline__ unsigned long long pack2(float lo, float hi) {
    unsigned long long r;
    asm("mov.b64 %0, {%1, %2};" : "=l"(r) : "f"(lo), "f"(hi));
    return r;
}
__device__ __forceinline__ void unpack2(unsigned long long v, float& lo, float& hi) {
    asm("mov.b64 {%0, %1}, %2;" : "=f"(lo), "=f"(hi) : "l"(v));
}
__device__ __forceinline__ unsigned long long ffma2(unsigned long long a,
                                                    unsigned long long b,
                                                    unsigned long long c) {
    unsigned long long d;
    asm("fma.rn.f32x2 %0, %1, %2, %3;" : "=l"(d) : "l"(a), "l"(b), "l"(c));
    return d;
}

// ---------------- kernel 0: fold tiny weights (1 block) ----------------
__global__ void precompute_small(const float* __restrict__ fm, const float* __restrict__ fs,
                                 const float* __restrict__ Wq, const float* __restrict__ bq,
                                 const float* __restrict__ Wk1,
                                 const float* __restrict__ Wqi, const float* __restrict__ bqi,
                                 const float* __restrict__ Wki,
                                 const float* __restrict__ bg, const float* __restrict__ bp) {
    __shared__ float sWcomb[32 * 64];  // Wqi @ Wq
    __shared__ float sb[32];           // Wqi @ bq + bqi
    __shared__ float su[32];           // Wki @ Wk1
    int tid = threadIdx.x;  // 256

    for (int i = tid; i < D_DIM * F_DIM; i += 256) g_f[i] = fm[i] * fs[i];

    for (int i = tid; i < 2048; i += 256) {
        int e = i >> 6, d = i & 63;
        float s = 0.f;
        #pragma unroll 8
        for (int a = 0; a < 32; a++) s += Wqi[e * 32 + a] * Wq[a * 64 + d];
        sWcomb[e * 64 + d] = s;
    }
    if (tid < 32) {
        float s = 0.f, uu = 0.f;
        for (int a = 0; a < 32; a++) {
            s += Wqi[tid * 32 + a] * bq[a];
            uu += Wki[tid * 32 + a] * Wk1[a];
        }
        sb[tid] = s + bqi[tid];
        su[tid] = uu;
    }
    if (tid < NOUT) g_ball[tid] = (tid < 64) ? bg[tid] : bp[tid - 64];
    __syncthreads();

    const float rs8 = 0.35355339059327373f;  // 1/sqrt(8)
    {
        int h = tid >> 6, d = tid & 63;  // 4*64 = 256 exactly
        float s = 0.f;
        #pragma unroll
        for (int e = 0; e < 8; e++) s += sWcomb[(h * 8 + e) * 64 + d] * su[h * 8 + e];
        g_walpha[h * 64 + d] = s * rs8;
    }
    if (tid < 4) {
        float s = 0.f;
        #pragma unroll
        for (int e = 0; e < 8; e++) s += sb[tid * 8 + e] * su[tid * 8 + e];
        g_calpha[tid] = s * rs8;
    }
}

// ---------------- kernel 1: pack Wg|Wp into [k][o] layout ----------------
__global__ void pack_weights(const float* __restrict__ Wg, const float* __restrict__ Wp) {
    int i = blockIdx.x * blockDim.x + threadIdx.x;
    if (i >= DIN * NOUT) return;
    int k = i >> 7, o = i & 127;
    g_Wpack[(size_t)k * NOUT + o] = (o < 64) ? Wg[(size_t)o * DIN + k]
                                             : Wp[(size_t)(o - 64) * DIN + k];
}

// ---------------- kernel 2: trig table [s][d][sin16|cos16] ----------------
__global__ void trig_table(const float* __restrict__ phase) {
    int i = blockIdx.x * blockDim.x + threadIdx.x;  // S*D*F = 2M
    if (i >= S_LEN * D_DIM * F_DIM) return;
    int f = i & 15, d = (i >> 4) & 63, s = i >> 10;
    float t = (float)s * (1.0f / (float)(S_LEN - 1));
    float sig = 6.283185307179586f * t * g_f[d * 16 + f] + phase[d * 16 + f];
    float sv, cv;
    sincosf(sig, &sv, &cv);
    size_t base = ((size_t)s * 64 + d) * 32;
    g_trig[base + f] = sv;
    g_trig[base + 16 + f] = cv;
}

// ---------------- kernel 3: fused feature + GEMM + gating ----------------
// 256 CTAs, 256 threads. CTA = 64 tokens x 128 outputs, K streamed in 66 chunks of 32.
__global__ void __launch_bounds__(256, 2)
fused_main(const float* __restrict__ x, float* __restrict__ out) {
    __shared__ __align__(16) float xs[64 * 64];   // [d][t]  x tile (transposed)
    __shared__ __align__(16) float As[32 * 64];   // [k][t]  feature chunk
    __shared__ __align__(16) float Ws[32 * 128];  // [k][o]  weight chunk

    int tid = threadIdx.x;
    int tokBase = blockIdx.x * 64;
    int sBase = tokBase & (S_LEN - 1);  // tile never crosses batch boundary (2048 % 64 == 0)
    const float* xb = x + (size_t)tokBase * 64;

    // load x tile, transpose into [d][t]
    for (int i = tid; i < 1024; i += 256) {
        float4 v = ((const float4*)xb)[i];
        int t = i >> 4, d0 = (i & 15) << 2;
        xs[(d0 + 0) * 64 + t] = v.x;
        xs[(d0 + 1) * 64 + t] = v.y;
        xs[(d0 + 2) * 64 + t] = v.z;
        xs[(d0 + 3) * 64 + t] = v.w;
    }
    __syncthreads();

    // per-thread alpha: thread = (token tt, head hh)
    int tt = tid >> 2, hh = tid & 3;
    float aval;
    {
        const float* wa = g_walpha + hh * 64;
        float s = __ldg(&g_calpha[hh]);
        #pragma unroll 16
        for (int d = 0; d < 64; d++) s += xs[d * 64 + tt] * __ldg(wa + d);
        aval = s;
    }

    // GEMM mapping: thread = (token group tg -> 8 tokens, output group og -> 4 outputs)
    int og = tid & 31, tg = tid >> 5;
    int t0 = tg * 8, o0 = og * 4;

    unsigned long long acc[16];  // acc[oi*4 + p] = C[token-pair p][output oi], bias-initialized
    #pragma unroll
    for (int oi = 0; oi < 4; oi++) {
        float b = __ldg(&g_ball[o0 + oi]);
        unsigned long long pb = pack2(b, b);
        acc[oi * 4 + 0] = pb; acc[oi * 4 + 1] = pb;
        acc[oi * 4 + 2] = pb; acc[oi * 4 + 3] = pb;
    }

    // prefetch weight chunk 0 into registers
    float4 pre[4];
    {
        const float4* ws = (const float4*)g_Wpack;
        #pragma unroll
        for (int j = 0; j < 4; j++) pre[j] = __ldg(ws + tid + 256 * j);
    }

    for (int iter = 0; iter < NITER; iter++) {
        __syncthreads();  // previous compute done reading As/Ws

        // commit prefetched weights to smem
        {
            float4* wd = (float4*)Ws;
            #pragma unroll
            for (int j = 0; j < 4; j++) wd[tid + 256 * j] = pre[j];
        }

        const float* Aptr;
        if (iter < 2) {
            Aptr = xs + iter * 2048;  // raw x part of ci
        } else {
            // produce fourier-feature chunk for d = iter-2
            int d = iter - 2;
            const float* fv = g_f + d * 16;
            float pr[16];
            float m = -1e30f;
            #pragma unroll
            for (int f_ = 0; f_ < 16; f_++) {
                pr[f_] = __ldg(fv + f_) * aval;
                m = fmaxf(m, pr[f_]);
            }
            float ss = 0.f;
            #pragma unroll
            for (int f_ = 0; f_ < 16; f_++) {
                pr[f_] = __expf(pr[f_] - m);
                ss += pr[f_];
            }
            float inv = 0.25f / ss;  // head-average factor folded in
            #pragma unroll
            for (int f_ = 0; f_ < 16; f_++) {
                float v = pr[f_] * inv;
                v += __shfl_xor_sync(0xFFFFFFFFu, v, 1);  // sum over 4 heads
                v += __shfl_xor_sync(0xFFFFFFFFu, v, 2);
                pr[f_] = v;  // = aw[token][f]
            }
            // each head-lane writes 8 of the 32 features: [sin0..15 | cos0..15]
            const float4* tb =
                (const float4*)(g_trig + ((size_t)(sBase + tt) * 64 + d) * 32) + hh * 2;
            float4 v0 = __ldg(tb), v1 = __ldg(tb + 1);
            int ab = (hh & 1) << 3;
            float* dst = As + hh * 8 * 64 + tt;
            dst[0]   = v0.x * pr[ab + 0];
            dst[64]  = v0.y * pr[ab + 1];
            dst[128] = v0.z * pr[ab + 2];
            dst[192] = v0.w * pr[ab + 3];
            dst[256] = v1.x * pr[ab + 4];
            dst[320] = v1.y * pr[ab + 5];
            dst[384] = v1.z * pr[ab + 6];
            dst[448] = v1.w * pr[ab + 7];
            Aptr = As;
        }
        __syncthreads();

        // prefetch next weight chunk (overlaps FMA loop)
        if (iter + 1 < NITER) {
            int nr = (iter + 1 < 2) ? (iter + 1) * 32 : 32 + iter * 32;  // 64+(iter-1)*32
            const float4* ws = (const float4*)(g_Wpack + (size_t)nr * NOUT);
            #pragma unroll
            for (int j = 0; j < 4; j++) pre[j] = __ldg(ws + tid + 256 * j);
        }

        // 32-step rank-1 updates, packed f32x2 (2 tokens per FMA)
        #pragma unroll 4
        for (int k = 0; k < 32; k++) {
            ulonglong2 a01 = *(const ulonglong2*)(Aptr + k * 64 + t0);       // tokens 0..3
            ulonglong2 a23 = *(const ulonglong2*)(Aptr + k * 64 + t0 + 4);   // tokens 4..7
            float4 wv = *(const float4*)(Ws + k * 128 + o0);
            unsigned long long b0 = pack2(wv.x, wv.x), b1 = pack2(wv.y, wv.y);
            unsigned long long b2 = pack2(wv.z, wv.z), b3 = pack2(wv.w, wv.w);
            acc[0]  = ffma2(a01.x, b0, acc[0]);  acc[1]  = ffma2(a01.y, b0, acc[1]);
            acc[2]  = ffma2(a23.x, b0, acc[2]);  acc[3]  = ffma2(a23.y, b0, acc[3]);
            acc[4]  = ffma2(a01.x, b1, acc[4]);  acc[5]  = ffma2(a01.y, b1, acc[5]);
            acc[6]  = ffma2(a23.x, b1, acc[6]);  acc[7]  = ffma2(a23.y, b1, acc[7]);
            acc[8]  = ffma2(a01.x, b2, acc[8]);  acc[9]  = ffma2(a01.y, b2, acc[9]);
            acc[10] = ffma2(a23.x, b2, acc[10]); acc[11] = ffma2(a23.y, b2, acc[11]);
            acc[12] = ffma2(a01.x, b3, acc[12]); acc[13] = ffma2(a01.y, b3, acc[13]);
            acc[14] = ffma2(a23.x, b3, acc[14]); acc[15] = ffma2(a23.y, b3, acc[15]);
        }
    }

    // epilogue: lane og holds gate outputs (og<16) / proj outputs (og>=16) for same o%64
    #pragma unroll
    for (int oi = 0; oi < 4; oi++) {
        #pragma unroll
        for (int p_ = 0; p_ < 4; p_++) {
            float lo, hi;
            unpack2(acc[oi * 4 + p_], lo, hi);
            float plo = __shfl_xor_sync(0xFFFFFFFFu, lo, 16);
            float phi = __shfl_xor_sync(0xFFFFFFFFu, hi, 16);
            if (og < 16) {
                int o = o0 + oi;       // 0..63
                int ta = t0 + 2 * p_;  // token pair
                float g0 = __frcp_rn(1.f + __expf(-lo));
                float s0 = plo * __frcp_rn(1.f + __expf(-plo));  // silu
                out[(size_t)(tokBase + ta) * 64 + o] = xs[o * 64 + ta] + g0 * s0;
                float g1 = __frcp_rn(1.f + __expf(-hi));
                float s1 = phi * __frcp_rn(1.f + __expf(-phi));
                out[(size_t)(tokBase + ta + 1) * 64 + o] = xs[o * 64 + ta + 1] + g1 * s1;
            }
        }
    }
}

// ---------------- launch ----------------
extern "C" void kernel_launch(void* const* d_in, const int* in_sizes, int n_in,
                              void* d_out, int out_size) {
    const float* x     = (const float*)d_in[0];
    const float* fm    = (const float*)d_in[1];
    const float* phase = (const float*)d_in[2];
    const float* fsc   = (const float*)d_in[3];
    const float* Wq    = (const float*)d_in[4];
    const float* bq    = (const float*)d_in[5];
    const float* Wk1   = (const float*)d_in[6];
    // d_in[7] = bk1: drops out of softmax (constant along f axis)
    const float* Wqi   = (const float*)d_in[8];
    const float* bqi   = (const float*)d_in[9];
    const float* Wki   = (const float*)d_in[10];
    // d_in[11] = bki: drops out of softmax
    const float* Wg    = (const float*)d_in[12];
    const float* bg    = (const float*)d_in[13];
    const float* Wp    = (const float*)d_in[14];
    const float* bp    = (const float*)d_in[15];
    float* out = (float*)d_out;

    precompute_small<<<1, 256>>>(fm, fsc, Wq, bq, Wk1, Wqi, bqi, Wki, bg, bp);
    pack_weights<<<(DIN * NOUT + 255) / 256, 256>>>(Wg, Wp);
    trig_table<<<(S_LEN * D_DIM * F_DIM + 255) / 256, 256>>>(phase);
    fused_main<<<NTOK / 64, 256>>>(x, out);
}

// round 4
// speedup vs baseline: 1.1173x; 1.1173x over previous
#include <cuda_runtime.h>
#include <math.h>

// Problem constants
#define S_LEN 2048
#define D_DIM 64
#define F_DIM 16
#define NTOK  16384      // B*S = 8*2048
#define DIN   2112       // D + 2*D*F
#define NOUT  128        // O gate + O proj
#define NITER 66         // DIN/32
#define TILE_T 128       // tokens per CTA

// ---------------- device scratch (static, allocation-free) ----------------
__device__ float g_f[D_DIM * F_DIM];          // freq_matrix * freq_scale
__device__ float g_walpha[4 * D_DIM];         // [h][d] folded alpha weights (incl 1/sqrt(8))
__device__ float g_calpha[4];                 // alpha bias
__device__ float g_ball[NOUT];                // bg | bp
__device__ float g_Wpack[DIN * NOUT];         // [k][o]: o<64 -> Wg[o][k], else Wp[o-64][k]
__device__ float g_trig[S_LEN * D_DIM * 32];  // [s][d][ sin(16) | cos(16) ]

// ---------------- f32x2 helpers (packed dual fp32 FMA, sm_100+) ----------------
__device__ __forceinline__ unsigned long long pack2(float lo, float hi) {
    unsigned long long r;
    asm("mov.b64 %0, {%1, %2};" : "=l"(r) : "f"(lo), "f"(hi));
    return r;
}
__device__ __forceinline__ void unpack2(unsigned long long v, float& lo, float& hi) {
    asm("mov.b64 {%0, %1}, %2;" : "=f"(lo), "=f"(hi) : "l"(v));
}
__device__ __forceinline__ unsigned long long ffma2(unsigned long long a,
                                                    unsigned long long b,
                                                    unsigned long long c) {
    unsigned long long d;
    asm("fma.rn.f32x2 %0, %1, %2, %3;" : "=l"(d) : "l"(a), "l"(b), "l"(c));
    return d;
}

// Column permutation: token tau -> column so that 16 lanes (tg=0..15) reading
// their 4-token 16B chunk form two dense 128B lines (conflict-free LDS.128).
// lo half (j<4)  -> col = tg*4 + j       (cols 0..63)
// hi half (j>=4) -> col = 64 + tg*4 + j-4 (cols 64..127)
__device__ __forceinline__ int pcol(int t) {
    return ((t & 4) << 4) + ((t >> 3) << 2) + (t & 3);
}

// ---------------- kernel 0: fold tiny weights (1 block) ----------------
__global__ void precompute_small(const float* __restrict__ fm, const float* __restrict__ fs,
                                 const float* __restrict__ Wq, const float* __restrict__ bq,
                                 const float* __restrict__ Wk1,
                                 const float* __restrict__ Wqi, const float* __restrict__ bqi,
                                 const float* __restrict__ Wki,
                                 const float* __restrict__ bg, const float* __restrict__ bp) {
    __shared__ float sWcomb[32 * 64];  // Wqi @ Wq
    __shared__ float sb[32];           // Wqi @ bq + bqi
    __shared__ float su[32];           // Wki @ Wk1
    int tid = threadIdx.x;  // 256

    for (int i = tid; i < D_DIM * F_DIM; i += 256) g_f[i] = fm[i] * fs[i];

    for (int i = tid; i < 2048; i += 256) {
        int e = i >> 6, d = i & 63;
        float s = 0.f;
        #pragma unroll 8
        for (int a = 0; a < 32; a++) s += Wqi[e * 32 + a] * Wq[a * 64 + d];
        sWcomb[e * 64 + d] = s;
    }
    if (tid < 32) {
        float s = 0.f, uu = 0.f;
        for (int a = 0; a < 32; a++) {
            s += Wqi[tid * 32 + a] * bq[a];
            uu += Wki[tid * 32 + a] * Wk1[a];
        }
        sb[tid] = s + bqi[tid];
        su[tid] = uu;
    }
    if (tid < NOUT) g_ball[tid] = (tid < 64) ? bg[tid] : bp[tid - 64];
    __syncthreads();

    const float rs8 = 0.35355339059327373f;  // 1/sqrt(8)
    {
        int h = tid >> 6, d = tid & 63;  // 4*64 = 256 exactly
        float s = 0.f;
        #pragma unroll
        for (int e = 0; e < 8; e++) s += sWcomb[(h * 8 + e) * 64 + d] * su[h * 8 + e];
        g_walpha[h * 64 + d] = s * rs8;
    }
    if (tid < 4) {
        float s = 0.f;
        #pragma unroll
        for (int e = 0; e < 8; e++) s += sb[tid * 8 + e] * su[tid * 8 + e];
        g_calpha[tid] = s * rs8;
    }
}

// ---------------- kernel 1: pack Wg|Wp into [k][o] layout ----------------
__global__ void pack_weights(const float* __restrict__ Wg, const float* __restrict__ Wp) {
    int i = blockIdx.x * blockDim.x + threadIdx.x;
    if (i >= DIN * NOUT) return;
    int k = i >> 7, o = i & 127;
    g_Wpack[(size_t)k * NOUT + o] = (o < 64) ? Wg[(size_t)o * DIN + k]
                                             : Wp[(size_t)(o - 64) * DIN + k];
}

// ---------------- kernel 2: trig table [s][d][sin16|cos16] ----------------
__global__ void trig_table(const float* __restrict__ phase) {
    int i = blockIdx.x * blockDim.x + threadIdx.x;  // S*D*F = 2M
    if (i >= S_LEN * D_DIM * F_DIM) return;
    int f = i & 15, d = (i >> 4) & 63, s = i >> 10;
    float t = (float)s * (1.0f / (float)(S_LEN - 1));
    float sig = 6.283185307179586f * t * g_f[d * 16 + f] + phase[d * 16 + f];
    float sv, cv;
    sincosf(sig, &sv, &cv);
    size_t base = ((size_t)s * 64 + d) * 32;
    g_trig[base + f] = sv;
    g_trig[base + 16 + f] = cv;
}

// ---------------- kernel 3: fused feature + GEMM + gating ----------------
// grid = 128 CTAs (one per SM, balanced), 256 threads.
// CTA tile: 128 tokens x 128 outputs. Thread tile: 8 tokens x (4 gate + 4 proj).
__global__ void __launch_bounds__(256, 1)
fused_main(const float* __restrict__ x, float* __restrict__ out) {
    __shared__ __align__(16) float xs[64 * 128];  // 32KB [d][pcol(t)]; rows 0-31 reused as As
    __shared__ __align__(16) float Ws[32 * 128];  // 16KB [k][o]
    float* As = xs;  // alias: feature chunk overwrites x rows 0-31 (consumed in iter 0)

    int tid = threadIdx.x;
    int tokBase = blockIdx.x * TILE_T;
    int sBase = tokBase & (S_LEN - 1);  // 2048 % 128 == 0: tile within one sequence
    const float* xb = x + (size_t)tokBase * 64;

    // ---- load x tile, transpose into [d][pcol(t)] ----
    #pragma unroll
    for (int r = 0; r < 8; r++) {
        int i = tid + 256 * r;
        float4 v = ((const float4*)xb)[i];
        int tau = i >> 4, d0 = (i & 15) << 2;
        int pc = pcol(tau);
        xs[(d0 + 0) * 128 + pc] = v.x;
        xs[(d0 + 1) * 128 + pc] = v.y;
        xs[(d0 + 2) * 128 + pc] = v.z;
        xs[(d0 + 3) * 128 + pc] = v.w;
    }
    __syncthreads();

    // ---- per-thread alpha: thread = (token taua, head-half h2); h2 owns heads {2h2, 2h2+1}
    int taua = tid >> 1, h2 = tid & 1;
    int pca = pcol(taua);
    float a0 = __ldg(&g_calpha[2 * h2]);
    float a1 = __ldg(&g_calpha[2 * h2 + 1]);
    {
        const float* wa = g_walpha + (2 * h2) * 64;
        #pragma unroll 8
        for (int d = 0; d < 64; d++) {
            float xv = xs[d * 128 + pca];
            a0 = fmaf(xv, __ldg(wa + d), a0);
            a1 = fmaf(xv, __ldg(wa + 64 + d), a1);
        }
    }

    // ---- GEMM mapping: warp w covers output groups {2w, 2w+1}; lanes 0-15 og=2w, 16-31 og=2w+1
    int lane = tid & 31, w = tid >> 5;
    int og = 2 * w + (lane >> 4);
    int tg = lane & 15;
    int o0 = og * 4, t0 = tg * 8;

    // accumulators: [oi][token-pair], f32x2 packs two adjacent tokens
    unsigned long long accG[4][4], accP[4][4];
    #pragma unroll
    for (int oi = 0; oi < 4; oi++) {
        float bgv = __ldg(&g_ball[o0 + oi]);
        float bpv = __ldg(&g_ball[64 + o0 + oi]);
        unsigned long long pg = pack2(bgv, bgv), pp = pack2(bpv, bpv);
        #pragma unroll
        for (int p = 0; p < 4; p++) { accG[oi][p] = pg; accP[oi][p] = pp; }
    }

    // prefetch weight chunk 0
    float4 pre[4];
    {
        const float4* ws = (const float4*)g_Wpack;
        #pragma unroll
        for (int j = 0; j < 4; j++) pre[j] = __ldg(ws + tid + 256 * j);
    }

    float vv[16];     // attention-weighted softmax (head-avg), for next produce
    float4 tpre[4];   // prefetched trig row (sin16 or cos16 half)

    for (int iter = 0; iter < NITER; iter++) {
        __syncthreads();  // previous GEMM done reading As/Ws

        // commit prefetched weights to smem
        {
            float4* wd = (float4*)Ws;
            #pragma unroll
            for (int j = 0; j < 4; j++) wd[tid + 256 * j] = pre[j];
        }

        const float* Aptr;
        if (iter < 2) {
            Aptr = xs + iter * 32 * 128;  // raw x rows
        } else {
            // write fourier features for d=iter-2: rows h2*16 .. +15, column pca
            float* dst = As + (h2 * 16) * 128 + pca;
            const float* tp = (const float*)tpre;
            #pragma unroll
            for (int j = 0; j < 16; j++) dst[j * 128] = tp[j] * vv[j];
            Aptr = As;
        }
        __syncthreads();

        // prefetch next weight chunk (overlaps GEMM)
        if (iter + 1 < NITER) {
            const float4* ws = (const float4*)(g_Wpack + (size_t)(iter + 1) * 32 * NOUT);
            #pragma unroll
            for (int j = 0; j < 4; j++) pre[j] = __ldg(ws + tid + 256 * j);
        }

        // softmax + trig prefetch for NEXT iter's produce (d_next = iter-1); no sync
        // between here and the GEMM below, so MUFU/LDG overlap FMA across warps.
        if (iter >= 1 && iter <= 64) {
            int dn = iter - 1;
            const float4* tb = (const float4*)(g_trig +
                ((size_t)(sBase + taua) * 64 + dn) * 32 + h2 * 16);
            #pragma unroll
            for (int j = 0; j < 4; j++) tpre[j] = __ldg(tb + j);

            const float* fv = g_f + dn * 16;
            float pr0[16], pr1[16];
            float m0 = -1e30f, m1 = -1e30f;
            #pragma unroll
            for (int f_ = 0; f_ < 16; f_++) {
                float fw = __ldg(fv + f_);
                pr0[f_] = fw * a0; m0 = fmaxf(m0, pr0[f_]);
                pr1[f_] = fw * a1; m1 = fmaxf(m1, pr1[f_]);
            }
            float s0 = 0.f, s1 = 0.f;
            #pragma unroll
            for (int f_ = 0; f_ < 16; f_++) {
                pr0[f_] = __expf(pr0[f_] - m0); s0 += pr0[f_];
                pr1[f_] = __expf(pr1[f_] - m1); s1 += pr1[f_];
            }
            float i0 = 0.25f / s0, i1 = 0.25f / s1;
            #pragma unroll
            for (int f_ = 0; f_ < 16; f_++) {
                float v = pr0[f_] * i0 + pr1[f_] * i1;
                v += __shfl_xor_sync(0xFFFFFFFFu, v, 1);  // sum other 2 heads (partner lane)
                vv[f_] = v;
            }
        }

        // ---- GEMM: 32 rank-1 updates ----
        #pragma unroll 8
        for (int k = 0; k < 32; k++) {
            ulonglong2 alo = *(const ulonglong2*)(Aptr + k * 128 + tg * 4);       // tokens t0..t0+3
            ulonglong2 ahi = *(const ulonglong2*)(Aptr + k * 128 + 64 + tg * 4);  // tokens t0+4..7
            float4 wg = *(const float4*)(Ws + k * 128 + o0);        // gate weights (broadcast)
            float4 wp = *(const float4*)(Ws + k * 128 + 64 + o0);   // proj weights (broadcast)
            unsigned long long g0 = pack2(wg.x, wg.x), g1 = pack2(wg.y, wg.y);
            unsigned long long g2 = pack2(wg.z, wg.z), g3 = pack2(wg.w, wg.w);
            unsigned long long q0 = pack2(wp.x, wp.x), q1 = pack2(wp.y, wp.y);
            unsigned long long q2 = pack2(wp.z, wp.z), q3 = pack2(wp.w, wp.w);
            accG[0][0] = ffma2(alo.x, g0, accG[0][0]); accG[0][1] = ffma2(alo.y, g0, accG[0][1]);
            accG[0][2] = ffma2(ahi.x, g0, accG[0][2]); accG[0][3] = ffma2(ahi.y, g0, accG[0][3]);
            accG[1][0] = ffma2(alo.x, g1, accG[1][0]); accG[1][1] = ffma2(alo.y, g1, accG[1][1]);
            accG[1][2] = ffma2(ahi.x, g1, accG[1][2]); accG[1][3] = ffma2(ahi.y, g1, accG[1][3]);
            accG[2][0] = ffma2(alo.x, g2, accG[2][0]); accG[2][1] = ffma2(alo.y, g2, accG[2][1]);
            accG[2][2] = ffma2(ahi.x, g2, accG[2][2]); accG[2][3] = ffma2(ahi.y, g2, accG[2][3]);
            accG[3][0] = ffma2(alo.x, g3, accG[3][0]); accG[3][1] = ffma2(alo.y, g3, accG[3][1]);
            accG[3][2] = ffma2(ahi.x, g3, accG[3][2]); accG[3][3] = ffma2(ahi.y, g3, accG[3][3]);
            accP[0][0] = ffma2(alo.x, q0, accP[0][0]); accP[0][1] = ffma2(alo.y, q0, accP[0][1]);
            accP[0][2] = ffma2(ahi.x, q0, accP[0][2]); accP[0][3] = ffma2(ahi.y, q0, accP[0][3]);
            accP[1][0] = ffma2(alo.x, q1, accP[1][0]); accP[1][1] = ffma2(alo.y, q1, accP[1][1]);
            accP[1][2] = ffma2(ahi.x, q1, accP[1][2]); accP[1][3] = ffma2(ahi.y, q1, accP[1][3]);
            accP[2][0] = ffma2(alo.x, q2, accP[2][0]); accP[2][1] = ffma2(alo.y, q2, accP[2][1]);
            accP[2][2] = ffma2(ahi.x, q2, accP[2][2]); accP[2][3] = ffma2(ahi.y, q2, accP[2][3]);
            accP[3][0] = ffma2(alo.x, q3, accP[3][0]); accP[3][1] = ffma2(alo.y, q3, accP[3][1]);
            accP[3][2] = ffma2(ahi.x, q3, accP[3][2]); accP[3][3] = ffma2(ahi.y, q3, accP[3][3]);
        }
    }

    // ---- epilogue: combine gate/proj locally, add residual (x reloaded from L2) ----
    #pragma unroll
    for (int p = 0; p < 4; p++) {
        float gl[4], gh[4], pl[4], ph[4];
        #pragma unroll
        for (int oi = 0; oi < 4; oi++) {
            unpack2(accG[oi][p], gl[oi], gh[oi]);
            unpack2(accP[oi][p], pl[oi], ph[oi]);
        }
        #pragma unroll
        for (int half = 0; half < 2; half++) {
            int tau = t0 + 2 * p + half;
            const float* xr = x + (size_t)(tokBase + tau) * 64 + o0;
            float4 xv = __ldg((const float4*)xr);
            float4 ov;
            float g, pv;
            g = half ? gh[0] : gl[0]; pv = half ? ph[0] : pl[0];
            ov.x = xv.x + __frcp_rn(1.f + __expf(-g)) * (pv * __frcp_rn(1.f + __expf(-pv)));
            g = half ? gh[1] : gl[1]; pv = half ? ph[1] : pl[1];
            ov.y = xv.y + __frcp_rn(1.f + __expf(-g)) * (pv * __frcp_rn(1.f + __expf(-pv)));
            g = half ? gh[2] : gl[2]; pv = half ? ph[2] : pl[2];
            ov.z = xv.z + __frcp_rn(1.f + __expf(-g)) * (pv * __frcp_rn(1.f + __expf(-pv)));
            g = half ? gh[3] : gl[3]; pv = half ? ph[3] : pl[3];
            ov.w = xv.w + __frcp_rn(1.f + __expf(-g)) * (pv * __frcp_rn(1.f + __expf(-pv)));
            *((float4*)(out + (size_t)(tokBase + tau) * 64 + o0)) = ov;
        }
    }
}

// ---------------- launch ----------------
extern "C" void kernel_launch(void* const* d_in, const int* in_sizes, int n_in,
                              void* d_out, int out_size) {
    const float* x     = (const float*)d_in[0];
    const float* fm    = (const float*)d_in[1];
    const float* phase = (const float*)d_in[2];
    const float* fsc   = (const float*)d_in[3];
    const float* Wq    = (const float*)d_in[4];
    const float* bq    = (const float*)d_in[5];
    const float* Wk1   = (const float*)d_in[6];
    // d_in[7] = bk1: constant along softmax axis -> cancels
    const float* Wqi   = (const float*)d_in[8];
    const float* bqi   = (const float*)d_in[9];
    const float* Wki   = (const float*)d_in[10];
    // d_in[11] = bki: cancels in softmax
    const float* Wg    = (const float*)d_in[12];
    const float* bg    = (const float*)d_in[13];
    const float* Wp    = (const float*)d_in[14];
    const float* bp    = (const float*)d_in[15];
    float* out = (float*)d_out;

    precompute_small<<<1, 256>>>(fm, fsc, Wq, bq, Wk1, Wqi, bqi, Wki, bg, bp);
    pack_weights<<<(DIN * NOUT + 255) / 256, 256>>>(Wg, Wp);
    trig_table<<<(S_LEN * D_DIM * F_DIM + 255) / 256, 256>>>(phase);
    fused_main<<<NTOK / TILE_T, 256>>>(x, out);
}